// round 13
// baseline (speedup 1.0000x reference)
#include <cuda_runtime.h>
#include <math.h>

#define BB     32
#define TT     2048
#define HIDD   1024
#define OUTD   1024
#define DVV    1024
#define HALF   512
#define KSPLIT 32
#define KCH    32      // HIDD / KSPLIT
#define SCH    32      // t-chunk for scores blocks
#define TCH    64      // t-chunk for context partials
#define NCH    (TT / TCH)     // 32
#define MAX_SC (BB * (TT / SCH))   // 2048
#define MAX_CX (BB * (TT / TCH))   // 1024

// ---- scratch (__device__ globals; no allocation allowed) ----
__device__ float g_qpart[KSPLIT][BB][OUTD];   // query partials per k-split
__device__ float g_query[BB * OUTD];          // [B, OUT]
__device__ float g_weff[OUTD];                // W1 @ W2
__device__ float g_c0;                        // b1 . W2 + b2
__device__ float g_scores[BB * TT];           // raw scores (only t < sl written)
__device__ float g_cpart[NCH][BB][DVV];       // context partials per t-chunk
__device__ int2  g_wl_sc[MAX_SC];             // dense worklist for scores (b, t0)
__device__ int   g_n_sc;
__device__ int2  g_wl_cx[MAX_CX];             // dense worklist for ctxpart (b, t0)
__device__ int   g_n_cx;

__device__ __forceinline__ float tanh_approx(float x) {
    float y;
    asm("tanh.approx.f32 %0, %1;" : "=f"(y) : "f"(x));
    return y;
}

// ---------------------------------------------------------------------------
// Kernel 1: query partials. grid = (OUT/256, KSPLIT) = (4, 32), block = 256.
// Wq (4 MB) read from DRAM exactly once across the grid. FMA-bound.
// ---------------------------------------------------------------------------
__global__ void k_qpart(const float* __restrict__ hidden,
                        const float* __restrict__ Wq) {
    __shared__ float hs[KCH][BB];
    const int ks = blockIdx.y;
    const int k0 = ks * KCH;
    const int tid = threadIdx.x;

    for (int idx = tid; idx < KCH * BB; idx += 256) {
        const int k = idx >> 5;
        const int b = idx & 31;
        hs[k][b] = hidden[b * HIDD + k0 + k];
    }
    __syncthreads();

    const int o = blockIdx.x * 256 + tid;
    float acc[BB];
    #pragma unroll
    for (int b = 0; b < BB; b++) acc[b] = 0.f;

    #pragma unroll 4
    for (int k = 0; k < KCH; k++) {
        const float w = Wq[(size_t)(k0 + k) * OUTD + o];
        const float4* h4 = reinterpret_cast<const float4*>(hs[k]);
        #pragma unroll
        for (int b4 = 0; b4 < BB / 4; b4++) {
            const float4 h = h4[b4];
            acc[b4 * 4 + 0] = fmaf(h.x, w, acc[b4 * 4 + 0]);
            acc[b4 * 4 + 1] = fmaf(h.y, w, acc[b4 * 4 + 1]);
            acc[b4 * 4 + 2] = fmaf(h.z, w, acc[b4 * 4 + 2]);
            acc[b4 * 4 + 3] = fmaf(h.w, w, acc[b4 * 4 + 3]);
        }
    }
    #pragma unroll
    for (int b = 0; b < BB; b++)
        g_qpart[ks][b][o] = acc[b];
}

// ---------------------------------------------------------------------------
// Kernel 2 (fused): blocks [0,128)  -> w_eff = W1@W2 and c0
//                   blocks [128,160)-> reduce query partials + bq
//                   block  160      -> build dense worklists from seq_lens
// ---------------------------------------------------------------------------
__global__ void k_qred_weff(const float* __restrict__ bq,
                            const float* __restrict__ W1,
                            const float* __restrict__ b1,
                            const float* __restrict__ W2,
                            const float* __restrict__ b2,
                            const int* __restrict__ seq_lens) {
    if (blockIdx.x < 128) {
        __shared__ float w2s[HALF];
        for (int j = threadIdx.x; j < HALF; j += 256) w2s[j] = W2[j];
        __syncthreads();

        const int warp = threadIdx.x >> 5;
        const int lane = threadIdx.x & 31;
        const int k = blockIdx.x * 8 + warp;

        float acc = 0.f;
        const float* row = W1 + (size_t)k * HALF;
        #pragma unroll 4
        for (int j = lane; j < HALF; j += 32)
            acc = fmaf(row[j], w2s[j], acc);
        #pragma unroll
        for (int off = 16; off; off >>= 1)
            acc += __shfl_xor_sync(0xFFFFFFFFu, acc, off);
        if (lane == 0) g_weff[k] = acc;

        if (blockIdx.x == 0 && warp == 0) {
            float c = 0.f;
            for (int j = lane; j < HALF; j += 32)
                c = fmaf(b1[j], w2s[j], c);
            #pragma unroll
            for (int off = 16; off; off >>= 1)
                c += __shfl_xor_sync(0xFFFFFFFFu, c, off);
            if (lane == 0) g_c0 = c + b2[0];
        }
    } else if (blockIdx.x < 160) {
        const int b = blockIdx.x - 128;
        const int tid = threadIdx.x;
        #pragma unroll
        for (int j = 0; j < 4; j++) {
            const int oo = tid + j * 256;
            float acc = bq[oo];
            #pragma unroll
            for (int s = 0; s < KSPLIT; s++)
                acc += g_qpart[s][b][oo];
            g_query[b * OUTD + oo] = acc;
        }
    } else {
        // Worklist builders. warp 0 -> scores list, warp 1 -> ctx list.
        const int warp = threadIdx.x >> 5;
        const int lane = threadIdx.x & 31;
        if (warp > 1) return;
        const int ch = (warp == 0) ? SCH : TCH;
        const int sl = seq_lens[lane];   // lane == batch
        const int nb = (sl + ch - 1) / ch;

        // inclusive warp scan of nb
        int x = nb;
        #pragma unroll
        for (int off = 1; off < 32; off <<= 1) {
            const int y = __shfl_up_sync(0xFFFFFFFFu, x, off);
            if (lane >= off) x += y;
        }
        const int base = x - nb;   // exclusive prefix

        int2* wl = (warp == 0) ? g_wl_sc : g_wl_cx;
        for (int c = 0; c < nb; c++)
            wl[base + c] = make_int2(lane, c * ch);
        if (lane == 31) {
            if (warp == 0) g_n_sc = x;
            else           g_n_cx = x;
        }
    }
}

// ---------------------------------------------------------------------------
// Kernel 3: scores. 1D grid = MAX_SC blocks; active bids are the contiguous
// dense worklist [0, g_n_sc) -> RR placement balances per-SM load exactly.
// Each block: 32 t-rows (8 warps x 4 rows). Inner arithmetic = round-8 form.
// ---------------------------------------------------------------------------
__global__ void k_scores(const float* __restrict__ key,
                         const int* __restrict__ seq_lens) {
    const int bid = blockIdx.x;
    if (bid >= g_n_sc) return;
    const int2 e = g_wl_sc[bid];
    const int b  = e.x;
    const int t0 = e.y;
    const int sl = seq_lens[b];

    __shared__ float4 qs[OUTD / 4];
    __shared__ float4 ws[OUTD / 4];
    for (int k = threadIdx.x; k < OUTD / 4; k += 256) {
        qs[k] = reinterpret_cast<const float4*>(g_query + (size_t)b * OUTD)[k];
        ws[k] = reinterpret_cast<const float4*>(g_weff)[k];
    }
    __syncthreads();

    const int warp = threadIdx.x >> 5;
    const int lane = threadIdx.x & 31;
    const float c0 = g_c0;
    const int tbase = t0 + warp * 4;

    #pragma unroll
    for (int r = 0; r < 4; r++) {
        const int t = tbase + r;
        if (t >= sl) break;

        const float4* row = reinterpret_cast<const float4*>(
            key + ((size_t)b * TT + t) * OUTD);

        float acc0 = 0.f, acc1 = 0.f;
        #pragma unroll
        for (int i = 0; i < 8; i++) {
            const int idx = i * 32 + lane;
            const float4 kv = __ldcs(row + idx);   // read-once stream
            const float4 q  = qs[idx];
            const float4 w  = ws[idx];
            acc0 = fmaf(tanh_approx(kv.x + q.x), w.x, acc0);
            acc1 = fmaf(tanh_approx(kv.y + q.y), w.y, acc1);
            acc0 = fmaf(tanh_approx(kv.z + q.z), w.z, acc0);
            acc1 = fmaf(tanh_approx(kv.w + q.w), w.w, acc1);
        }
        float acc = acc0 + acc1;
        #pragma unroll
        for (int off = 16; off; off >>= 1)
            acc += __shfl_xor_sync(0xFFFFFFFFu, acc, off);
        if (lane == 0) g_scores[(size_t)b * TT + t] = acc + c0;
    }
}

// ---------------------------------------------------------------------------
// Kernel 4: softmax per batch. grid = B, block = 1024, shuffle reductions.
// ---------------------------------------------------------------------------
__global__ void k_softmax(const int* __restrict__ seq_lens,
                          float* __restrict__ attn) {
    __shared__ float wred[32];
    __shared__ float bmax;
    __shared__ float bsum;

    const int b    = blockIdx.x;
    const int sl   = seq_lens[b];
    const int tid  = threadIdx.x;
    const int lane = tid & 31;
    const int warp = tid >> 5;

    const float s0 = (tid        < sl) ? g_scores[(size_t)b * TT + tid]        : -INFINITY;
    const float s1 = (tid + 1024 < sl) ? g_scores[(size_t)b * TT + tid + 1024] : -INFINITY;

    float m = fmaxf(s0, s1);
    #pragma unroll
    for (int off = 16; off; off >>= 1)
        m = fmaxf(m, __shfl_xor_sync(0xFFFFFFFFu, m, off));
    if (lane == 0) wred[warp] = m;
    __syncthreads();
    if (warp == 0) {
        float v = wred[lane];
        #pragma unroll
        for (int off = 16; off; off >>= 1)
            v = fmaxf(v, __shfl_xor_sync(0xFFFFFFFFu, v, off));
        if (lane == 0) bmax = v;
    }
    __syncthreads();
    m = bmax;

    const float e0 = __expf(s0 - m);   // -inf -> 0 exactly
    const float e1 = __expf(s1 - m);
    float sum = e0 + e1;
    #pragma unroll
    for (int off = 16; off; off >>= 1)
        sum += __shfl_xor_sync(0xFFFFFFFFu, sum, off);
    if (lane == 0) wred[warp] = sum;
    __syncthreads();
    if (warp == 0) {
        float v = wred[lane];
        #pragma unroll
        for (int off = 16; off; off >>= 1)
            v += __shfl_xor_sync(0xFFFFFFFFu, v, off);
        if (lane == 0) bsum = v;
    }
    __syncthreads();
    const float inv = 1.0f / bsum;

    attn[(size_t)b * TT + tid]        = e0 * inv;
    attn[(size_t)b * TT + tid + 1024] = e1 * inv;
}

// ---------------------------------------------------------------------------
// Kernel 5: context partials. 1D grid = MAX_CX; dense worklist [0, g_n_cx).
// Each block: 64 t-rows x full 1024 d (thread -> float4).
// ---------------------------------------------------------------------------
__global__ void k_ctxpart(const float* __restrict__ value,
                          const int* __restrict__ seq_lens,
                          const float* __restrict__ attn) {
    const int bid = blockIdx.x;
    if (bid >= g_n_cx) return;
    const int2 e = g_wl_cx[bid];
    const int b  = e.x;
    const int t0 = e.y;
    const int sl = seq_lens[b];
    const int c  = t0 / TCH;

    __shared__ float as[TCH];
    const int tid = threadIdx.x;
    if (tid < TCH)
        as[tid] = attn[(size_t)b * TT + t0 + tid];   // 0 beyond sl
    __syncthreads();

    const int nt = min(TCH, sl - t0);
    const float4* vbase = reinterpret_cast<const float4*>(
        value + ((size_t)b * TT + t0) * DVV) + tid;

    float4 acc = {0.f, 0.f, 0.f, 0.f};
    #pragma unroll 16
    for (int t = 0; t < nt; t++) {
        const float  a = as[t];
        const float4 v = __ldcs(vbase + (size_t)t * (DVV / 4));
        acc.x = fmaf(a, v.x, acc.x);
        acc.y = fmaf(a, v.y, acc.y);
        acc.z = fmaf(a, v.z, acc.z);
        acc.w = fmaf(a, v.w, acc.w);
    }
    reinterpret_cast<float4*>(&g_cpart[c][b][0])[tid] = acc;
}

// ---------------------------------------------------------------------------
// Kernel 6: reduce context partials (fixed order -> deterministic).
// grid = B, block = 256, thread -> float4 of d.
// ---------------------------------------------------------------------------
__global__ void k_ctxred(const int* __restrict__ seq_lens,
                         float* __restrict__ context) {
    const int b   = blockIdx.x;
    const int sl  = seq_lens[b];
    const int nch = (sl + TCH - 1) / TCH;
    const int tid = threadIdx.x;

    float4 acc = {0.f, 0.f, 0.f, 0.f};
    for (int c = 0; c < nch; c++) {
        const float4 p = reinterpret_cast<const float4*>(&g_cpart[c][b][0])[tid];
        acc.x += p.x; acc.y += p.y; acc.z += p.z; acc.w += p.w;
    }
    reinterpret_cast<float4*>(context + (size_t)b * DVV)[tid] = acc;
}

// ---------------------------------------------------------------------------
extern "C" void kernel_launch(void* const* d_in, const int* in_sizes, int n_in,
                              void* d_out, int out_size) {
    const float* hidden   = (const float*)d_in[0];
    const float* key      = (const float*)d_in[1];
    const float* value    = (const float*)d_in[2];
    const int*   seq_lens = (const int*)  d_in[3];
    const float* Wq       = (const float*)d_in[4];
    const float* bq       = (const float*)d_in[5];
    const float* W1       = (const float*)d_in[6];
    const float* b1       = (const float*)d_in[7];
    const float* W2       = (const float*)d_in[8];
    const float* b2       = (const float*)d_in[9];

    float* out     = (float*)d_out;
    float* context = out;                 // [B, DV]
    float* attn    = out + BB * DVV;      // [B, T]

    k_qpart    <<<dim3(OUTD / 256, KSPLIT), 256>>>(hidden, Wq);
    k_qred_weff<<<161, 256>>>(bq, W1, b1, W2, b2, seq_lens);
    k_scores   <<<MAX_SC, 256>>>(key, seq_lens);
    k_softmax  <<<BB, 1024>>>(seq_lens, attn);
    k_ctxpart  <<<MAX_CX, 256>>>(value, seq_lens, attn);
    k_ctxred   <<<BB, 256>>>(seq_lens, context);
}

// round 15
// speedup vs baseline: 1.0295x; 1.0295x over previous
#include <cuda_runtime.h>
#include <math.h>

#define BB     32
#define TT     2048
#define HIDD   1024
#define OUTD   1024
#define DVV    1024
#define HALF   512
#define KSPLIT 32
#define KCH    32      // HIDD / KSPLIT
#define SCH    32      // t-chunk for scores blocks
#define TCH    64      // t-chunk for context partials
#define NCH    (TT / TCH)     // 32
#define MAX_SC (BB * (TT / SCH))   // 2048
#define MAX_CX (BB * (TT / TCH))   // 1024

// ---- scratch (__device__ globals; no allocation allowed) ----
__device__ float g_qpart[KSPLIT][BB][OUTD];   // query partials per k-split
__device__ float g_query[BB * OUTD];          // [B, OUT]
__device__ float g_weff[OUTD];                // W1 @ W2
__device__ float g_c0;                        // b1 . W2 + b2
__device__ float g_scores[BB * TT];           // raw scores (only t < sl written)
__device__ float g_cpart[NCH][BB][DVV];       // context partials per t-chunk
__device__ int2  g_wl_sc[MAX_SC];             // dense worklist for scores (b, t0)
__device__ int   g_n_sc;
__device__ int2  g_wl_cx[MAX_CX];             // dense worklist for ctxpart (b, t0)
__device__ int   g_n_cx;
__device__ int   g_ctr_sc[BB];                // per-batch done counters (scores)
__device__ int   g_ctr_cx[BB];                // per-batch done counters (ctx)

__device__ __forceinline__ float tanh_approx(float x) {
    float y;
    asm("tanh.approx.f32 %0, %1;" : "=f"(y) : "f"(x));
    return y;
}

// ---------------------------------------------------------------------------
// Kernel 1: query partials. grid = (OUT/256, KSPLIT) = (4, 32), block = 256.
// Block (0,0) also resets the per-batch completion counters for this replay.
// ---------------------------------------------------------------------------
__global__ void k_qpart(const float* __restrict__ hidden,
                        const float* __restrict__ Wq) {
    __shared__ float hs[KCH][BB];
    const int ks = blockIdx.y;
    const int k0 = ks * KCH;
    const int tid = threadIdx.x;

    if (blockIdx.x == 0 && blockIdx.y == 0 && tid < 2 * BB) {
        if (tid < BB) g_ctr_sc[tid] = 0;
        else          g_ctr_cx[tid - BB] = 0;
    }

    for (int idx = tid; idx < KCH * BB; idx += 256) {
        const int k = idx >> 5;
        const int b = idx & 31;
        hs[k][b] = hidden[b * HIDD + k0 + k];
    }
    __syncthreads();

    const int o = blockIdx.x * 256 + tid;
    float acc[BB];
    #pragma unroll
    for (int b = 0; b < BB; b++) acc[b] = 0.f;

    #pragma unroll 4
    for (int k = 0; k < KCH; k++) {
        const float w = Wq[(size_t)(k0 + k) * OUTD + o];
        const float4* h4 = reinterpret_cast<const float4*>(hs[k]);
        #pragma unroll
        for (int b4 = 0; b4 < BB / 4; b4++) {
            const float4 h = h4[b4];
            acc[b4 * 4 + 0] = fmaf(h.x, w, acc[b4 * 4 + 0]);
            acc[b4 * 4 + 1] = fmaf(h.y, w, acc[b4 * 4 + 1]);
            acc[b4 * 4 + 2] = fmaf(h.z, w, acc[b4 * 4 + 2]);
            acc[b4 * 4 + 3] = fmaf(h.w, w, acc[b4 * 4 + 3]);
        }
    }
    #pragma unroll
    for (int b = 0; b < BB; b++)
        g_qpart[ks][b][o] = acc[b];
}

// ---------------------------------------------------------------------------
// Kernel 2 (fused): blocks [0,128)  -> w_eff = W1@W2 and c0
//                   blocks [128,160)-> reduce query partials + bq
//                   block  160      -> build dense worklists from seq_lens
// ---------------------------------------------------------------------------
__global__ void k_qred_weff(const float* __restrict__ bq,
                            const float* __restrict__ W1,
                            const float* __restrict__ b1,
                            const float* __restrict__ W2,
                            const float* __restrict__ b2,
                            const int* __restrict__ seq_lens) {
    if (blockIdx.x < 128) {
        __shared__ float w2s[HALF];
        for (int j = threadIdx.x; j < HALF; j += 256) w2s[j] = W2[j];
        __syncthreads();

        const int warp = threadIdx.x >> 5;
        const int lane = threadIdx.x & 31;
        const int k = blockIdx.x * 8 + warp;

        float acc = 0.f;
        const float* row = W1 + (size_t)k * HALF;
        #pragma unroll 4
        for (int j = lane; j < HALF; j += 32)
            acc = fmaf(row[j], w2s[j], acc);
        #pragma unroll
        for (int off = 16; off; off >>= 1)
            acc += __shfl_xor_sync(0xFFFFFFFFu, acc, off);
        if (lane == 0) g_weff[k] = acc;

        if (blockIdx.x == 0 && warp == 0) {
            float c = 0.f;
            for (int j = lane; j < HALF; j += 32)
                c = fmaf(b1[j], w2s[j], c);
            #pragma unroll
            for (int off = 16; off; off >>= 1)
                c += __shfl_xor_sync(0xFFFFFFFFu, c, off);
            if (lane == 0) g_c0 = c + b2[0];
        }
    } else if (blockIdx.x < 160) {
        const int b = blockIdx.x - 128;
        const int tid = threadIdx.x;
        #pragma unroll
        for (int j = 0; j < 4; j++) {
            const int oo = tid + j * 256;
            float acc = bq[oo];
            #pragma unroll
            for (int s = 0; s < KSPLIT; s++)
                acc += g_qpart[s][b][oo];
            g_query[b * OUTD + oo] = acc;
        }
    } else {
        // Worklist builders. warp 0 -> scores list, warp 1 -> ctx list.
        const int warp = threadIdx.x >> 5;
        const int lane = threadIdx.x & 31;
        if (warp > 1) return;
        const int ch = (warp == 0) ? SCH : TCH;
        const int sl = seq_lens[lane];   // lane == batch
        const int nb = (sl + ch - 1) / ch;

        // inclusive warp scan of nb
        int x = nb;
        #pragma unroll
        for (int off = 1; off < 32; off <<= 1) {
            const int y = __shfl_up_sync(0xFFFFFFFFu, x, off);
            if (lane >= off) x += y;
        }
        const int base = x - nb;   // exclusive prefix

        int2* wl = (warp == 0) ? g_wl_sc : g_wl_cx;
        for (int c = 0; c < nb; c++)
            wl[base + c] = make_int2(lane, c * ch);
        if (lane == 31) {
            if (warp == 0) g_n_sc = x;
            else           g_n_cx = x;
        }
    }
}

// ---------------------------------------------------------------------------
// Kernel 3: scores + fused per-batch softmax (last-block pattern).
// Publication order: writers store -> each thread __threadfence() ->
// __syncthreads() -> tid0 atomicAdd. Last block acquires with a fence.
// ---------------------------------------------------------------------------
__global__ void k_scores(const float* __restrict__ key,
                         const int* __restrict__ seq_lens,
                         float* __restrict__ attn) {
    const int bid = blockIdx.x;
    if (bid >= g_n_sc) return;
    const int2 e = g_wl_sc[bid];
    const int b  = e.x;
    const int t0 = e.y;
    const int sl = seq_lens[b];

    __shared__ float4 qs[OUTD / 4];
    __shared__ float4 ws[OUTD / 4];
    for (int k = threadIdx.x; k < OUTD / 4; k += 256) {
        qs[k] = reinterpret_cast<const float4*>(g_query + (size_t)b * OUTD)[k];
        ws[k] = reinterpret_cast<const float4*>(g_weff)[k];
    }
    __syncthreads();

    const int warp = threadIdx.x >> 5;
    const int lane = threadIdx.x & 31;
    const float c0 = g_c0;
    const int tbase = t0 + warp * 4;

    #pragma unroll
    for (int r = 0; r < 4; r++) {
        const int t = tbase + r;
        if (t >= sl) break;

        const float4* row = reinterpret_cast<const float4*>(
            key + ((size_t)b * TT + t) * OUTD);

        float acc0 = 0.f, acc1 = 0.f;
        #pragma unroll
        for (int i = 0; i < 8; i++) {
            const int idx = i * 32 + lane;
            const float4 kv = __ldcs(row + idx);   // read-once stream
            const float4 q  = qs[idx];
            const float4 w  = ws[idx];
            acc0 = fmaf(tanh_approx(kv.x + q.x), w.x, acc0);
            acc1 = fmaf(tanh_approx(kv.y + q.y), w.y, acc1);
            acc0 = fmaf(tanh_approx(kv.z + q.z), w.z, acc0);
            acc1 = fmaf(tanh_approx(kv.w + q.w), w.w, acc1);
        }
        float acc = acc0 + acc1;
        #pragma unroll
        for (int off = 16; off; off >>= 1)
            acc += __shfl_xor_sync(0xFFFFFFFFu, acc, off);
        if (lane == 0) g_scores[(size_t)b * TT + t] = acc + c0;
    }

    // ---- publish + elect last block for batch b ----
    __threadfence();                    // each writer makes its stores visible
    __syncthreads();                    // tid0's atomic after ALL fences
    __shared__ int ticket;
    if (threadIdx.x == 0)
        ticket = atomicAdd(&g_ctr_sc[b], 1);
    __syncthreads();

    const int nb = (sl + SCH - 1) / SCH;
    if (ticket != nb - 1) return;
    __threadfence();                    // acquire other blocks' score writes

    // ---- softmax for batch b ----
    __shared__ float wred[8];
    __shared__ float bval;
    const int tid = threadIdx.x;

    float local[8];
    float m = -INFINITY;
    #pragma unroll
    for (int i = 0; i < 8; i++) {
        const int t = tid + i * 256;
        local[i] = (t < sl) ? g_scores[(size_t)b * TT + t] : -INFINITY;
        m = fmaxf(m, local[i]);
    }
    #pragma unroll
    for (int off = 16; off; off >>= 1)
        m = fmaxf(m, __shfl_xor_sync(0xFFFFFFFFu, m, off));
    if (lane == 0) wred[warp] = m;
    __syncthreads();
    if (warp == 0) {
        float v = (lane < 8) ? wred[lane] : -INFINITY;
        #pragma unroll
        for (int off = 4; off; off >>= 1)
            v = fmaxf(v, __shfl_xor_sync(0xFFFFFFFFu, v, off));
        if (lane == 0) bval = v;
    }
    __syncthreads();
    m = bval;
    __syncthreads();

    float sum = 0.f;
    #pragma unroll
    for (int i = 0; i < 8; i++) {
        local[i] = __expf(local[i] - m);   // -inf -> 0 exactly
        sum += local[i];
    }
    #pragma unroll
    for (int off = 16; off; off >>= 1)
        sum += __shfl_xor_sync(0xFFFFFFFFu, sum, off);
    if (lane == 0) wred[warp] = sum;
    __syncthreads();
    if (warp == 0) {
        float v = (lane < 8) ? wred[lane] : 0.f;
        #pragma unroll
        for (int off = 4; off; off >>= 1)
            v += __shfl_xor_sync(0xFFFFFFFFu, v, off);
        if (lane == 0) bval = v;
    }
    __syncthreads();
    const float inv = 1.0f / bval;

    #pragma unroll
    for (int i = 0; i < 8; i++)
        attn[(size_t)b * TT + tid + i * 256] = local[i] * inv;
}

// ---------------------------------------------------------------------------
// Kernel 4: context partials + fused per-batch reduction (last-block pattern).
// Same corrected publication order as k_scores. Reduction is fixed-order.
// ---------------------------------------------------------------------------
__global__ void k_ctxpart(const float* __restrict__ value,
                          const int* __restrict__ seq_lens,
                          const float* __restrict__ attn,
                          float* __restrict__ context) {
    const int bid = blockIdx.x;
    if (bid >= g_n_cx) return;
    const int2 e = g_wl_cx[bid];
    const int b  = e.x;
    const int t0 = e.y;
    const int sl = seq_lens[b];
    const int c  = t0 / TCH;

    __shared__ float as[TCH];
    const int tid = threadIdx.x;
    if (tid < TCH)
        as[tid] = attn[(size_t)b * TT + t0 + tid];   // 0 beyond sl
    __syncthreads();

    const int nt = min(TCH, sl - t0);
    const float4* vbase = reinterpret_cast<const float4*>(
        value + ((size_t)b * TT + t0) * DVV) + tid;

    float4 acc = {0.f, 0.f, 0.f, 0.f};
    #pragma unroll 16
    for (int t = 0; t < nt; t++) {
        const float  a = as[t];
        const float4 v = __ldcs(vbase + (size_t)t * (DVV / 4));
        acc.x = fmaf(a, v.x, acc.x);
        acc.y = fmaf(a, v.y, acc.y);
        acc.z = fmaf(a, v.z, acc.z);
        acc.w = fmaf(a, v.w, acc.w);
    }
    reinterpret_cast<float4*>(&g_cpart[c][b][0])[tid] = acc;

    // ---- publish + elect last block for batch b ----
    __threadfence();                    // each writer makes its partial visible
    __syncthreads();                    // tid0's atomic after ALL fences
    __shared__ int ticket;
    if (tid == 0)
        ticket = atomicAdd(&g_ctr_cx[b], 1);
    __syncthreads();

    const int nch = (sl + TCH - 1) / TCH;
    if (ticket != nch - 1) return;
    __threadfence();                    // acquire other blocks' partials

    float4 s = {0.f, 0.f, 0.f, 0.f};
    for (int cc = 0; cc < nch; cc++) {
        const float4 p = reinterpret_cast<const float4*>(&g_cpart[cc][b][0])[tid];
        s.x += p.x; s.y += p.y; s.z += p.z; s.w += p.w;
    }
    reinterpret_cast<float4*>(context + (size_t)b * DVV)[tid] = s;
}

// ---------------------------------------------------------------------------
extern "C" void kernel_launch(void* const* d_in, const int* in_sizes, int n_in,
                              void* d_out, int out_size) {
    const float* hidden   = (const float*)d_in[0];
    const float* key      = (const float*)d_in[1];
    const float* value    = (const float*)d_in[2];
    const int*   seq_lens = (const int*)  d_in[3];
    const float* Wq       = (const float*)d_in[4];
    const float* bq       = (const float*)d_in[5];
    const float* W1       = (const float*)d_in[6];
    const float* b1       = (const float*)d_in[7];
    const float* W2       = (const float*)d_in[8];
    const float* b2       = (const float*)d_in[9];

    float* out     = (float*)d_out;
    float* context = out;                 // [B, DV]
    float* attn    = out + BB * DVV;      // [B, T]

    k_qpart    <<<dim3(OUTD / 256, KSPLIT), 256>>>(hidden, Wq);
    k_qred_weff<<<161, 256>>>(bq, W1, b1, W2, b2, seq_lens);
    k_scores   <<<MAX_SC, 256>>>(key, seq_lens, attn);
    k_ctxpart  <<<MAX_CX, 256>>>(value, seq_lens, attn, context);
}